// round 1
// baseline (speedup 1.0000x reference)
#include <cuda_runtime.h>
#include <cstdint>

// Problem constants
#define B_  16
#define L_  64
#define F_  60
#define D_  256
#define U_  600
#define V_  10000
#define E_  7        // MAX_LEN - MIN_LEN + 1
#define NEGF (-1e9f)

// Scratch (device globals: no allocation allowed)
__device__ float g_wn[1024 * 256];          // normalized word reprs [B*L, D]
__device__ float g_un[600 * 256];           // normalized unit reprs [U, D]
__device__ float g_sim[1024 * 600];         // sim [B*L, U]
__device__ uint4 g_seg[10000 * 2];          // packed vocab: 10 u16 units, len, 1/len
__device__ unsigned long long g_keys[16];   // per-batch best candidate key

// ---------------------------------------------------------------------------
// Kernel 1: row = (x or unit_feats) @ W, then L2-normalize.  grid = 1024+600
// ---------------------------------------------------------------------------
__global__ void k_embed(const float* __restrict__ x,
                        const float* __restrict__ uf,
                        const float* __restrict__ W) {
    __shared__ float feat[F_];
    __shared__ float s_part[8];
    __shared__ float s_inv;
    int r = blockIdx.x;
    const float* src;
    float* dst;
    if (r < 1024) { src = x + r * F_;            dst = g_wn + r * D_; }
    else          { src = uf + (r - 1024) * F_;  dst = g_un + (r - 1024) * D_; }
    int d = threadIdx.x;             // 0..255 == D_
    if (d < F_) feat[d] = src[d];
    __syncthreads();
    float val = 0.f;
    #pragma unroll
    for (int f = 0; f < F_; f++) val = fmaf(feat[f], W[f * D_ + d], val);
    // block reduce sum of squares
    float v2 = val * val;
    #pragma unroll
    for (int o = 16; o; o >>= 1) v2 += __shfl_down_sync(0xffffffffu, v2, o);
    if ((d & 31) == 0) s_part[d >> 5] = v2;
    __syncthreads();
    if (d == 0) {
        float s = 0.f;
        #pragma unroll
        for (int i = 0; i < 8; i++) s += s_part[i];
        s_inv = 1.0f / (sqrtf(s) + 1e-8f);
    }
    __syncthreads();
    dst[d] = val * s_inv;
}

// ---------------------------------------------------------------------------
// Kernel 2: sim = wn @ un^T  (M=1024, N=600, K=256), classic 64x64 tile,
// 256 threads, 4x4 per thread.  grid = (ceil(600/64)=10, 1024/64=16)
// ---------------------------------------------------------------------------
__global__ void k_sim_gemm() {
    __shared__ float As[16 * 64];
    __shared__ float Bs[16 * 64];
    int tid = threadIdx.x;
    int n0 = blockIdx.x * 64;
    int m0 = blockIdx.y * 64;
    int tx = tid & 15, ty = tid >> 4;      // 16x16 thread grid
    int lm = tid >> 2;                     // 0..63 : row of tile to load
    int lk = (tid & 3) * 4;                // 0,4,8,12 : k-offset (float4)
    float acc[4][4] = {};
    for (int k0 = 0; k0 < 256; k0 += 16) {
        float4 a = *(const float4*)(g_wn + (m0 + lm) * 256 + k0 + lk);
        float4 bv = make_float4(0.f, 0.f, 0.f, 0.f);
        int n = n0 + lm;
        if (n < U_) bv = *(const float4*)(g_un + n * 256 + k0 + lk);
        __syncthreads();   // previous compute done before overwrite
        As[(lk + 0) * 64 + lm] = a.x;
        As[(lk + 1) * 64 + lm] = a.y;
        As[(lk + 2) * 64 + lm] = a.z;
        As[(lk + 3) * 64 + lm] = a.w;
        Bs[(lk + 0) * 64 + lm] = bv.x;
        Bs[(lk + 1) * 64 + lm] = bv.y;
        Bs[(lk + 2) * 64 + lm] = bv.z;
        Bs[(lk + 3) * 64 + lm] = bv.w;
        __syncthreads();
        #pragma unroll
        for (int kk = 0; kk < 16; kk++) {
            float ar[4], br[4];
            #pragma unroll
            for (int i = 0; i < 4; i++) ar[i] = As[kk * 64 + ty * 4 + i];
            #pragma unroll
            for (int j = 0; j < 4; j++) br[j] = Bs[kk * 64 + tx * 4 + j];
            #pragma unroll
            for (int i = 0; i < 4; i++)
                #pragma unroll
                for (int j = 0; j < 4; j++)
                    acc[i][j] = fmaf(ar[i], br[j], acc[i][j]);
        }
    }
    #pragma unroll
    for (int i = 0; i < 4; i++) {
        int m = m0 + ty * 4 + i;
        #pragma unroll
        for (int j = 0; j < 4; j++) {
            int n = n0 + tx * 4 + j;
            if (n < U_) g_sim[m * U_ + n] = acc[i][j];
        }
    }
}

// ---------------------------------------------------------------------------
// Kernel 3: pack vocab table: 10 u16 unit ids + len + 1/len  (32B / word)
// ---------------------------------------------------------------------------
__global__ void k_prep(const int* __restrict__ segs, const int* __restrict__ vlen) {
    int v = blockIdx.x * 256 + threadIdx.x;
    if (v >= V_) return;
    unsigned w[5];
    #pragma unroll
    for (int p = 0; p < 5; p++) {
        unsigned lo = (unsigned)segs[v * 10 + 2 * p];
        unsigned hi = (unsigned)segs[v * 10 + 2 * p + 1];
        w[p] = (lo & 0xFFFFu) | (hi << 16);
    }
    int len = vlen[v];
    float inv = 1.0f / (float)len;
    g_seg[v * 2]     = make_uint4(w[0], w[1], w[2], w[3]);
    g_seg[v * 2 + 1] = make_uint4(w[4], (unsigned)len, __float_as_uint(inv), 0u);
}

// monotone float->u32 (orders like float compare, all non-NaN)
__device__ __forceinline__ unsigned f2mono(float f) {
    unsigned b = __float_as_uint(f);
    return (b & 0x80000000u) ? ~b : (b | 0x80000000u);
}
__device__ __forceinline__ unsigned long long pack_key(float s, int f, int v) {
    return ((unsigned long long)f2mono(s) << 23)
         | ((unsigned long long)(511 - f) << 14)
         | (unsigned long long)(16383 - v);
}

__global__ void k_init_keys() {
    int t = threadIdx.x;
    if (t < B_) g_keys[t] = pack_key(NEGF, 0, 0);
}

// ---------------------------------------------------------------------------
// Kernel 4 (hot): per (b, 32-l tile, vocab chunk) CTA.
// smem holds sim rows [l0 .. l0+40] padded to stride 601 (odd mod 32 ->
// conflict-free when the 32 lanes = 32 consecutive l's gather the same unit).
// grid = (VCHUNK=8, 2, 16), block = 512 (16 warps).
// ---------------------------------------------------------------------------
#define PB_ROWS 41
#define PB_STRIDE 601
#define PB_SMEM (PB_ROWS * PB_STRIDE * 4)
#define NPARTS 128   // 8 chunks * 16 warps

__global__ void __launch_bounds__(512, 2) k_phaseB(const int* __restrict__ lengths) {
    extern __shared__ float S[];
    int vc = blockIdx.x;   // 0..7
    int lt = blockIdx.y;   // 0..1
    int b  = blockIdx.z;   // 0..15
    int l0 = lt * 32;
    const float* simb = g_sim + (b * L_) * U_;
    // stage sim tile (rows >= L_ are the zero padding of the reference)
    for (int i = threadIdx.x; i < PB_ROWS * U_; i += 512) {
        int r = i / U_;
        int u = i - r * U_;
        int gl = l0 + r;
        S[r * PB_STRIDE + u] = (gl < L_) ? simb[gl * U_ + u] : 0.f;
    }
    __syncthreads();

    int warp = threadIdx.x >> 5;
    int lane = threadIdx.x & 31;
    int l = l0 + lane;
    int Lb = __ldg(&lengths[b]);
    const float* base = S + lane * PB_STRIDE;

    int part = vc * 16 + warp;
    int vlo = (part * V_) / NPARTS;
    int vhi = ((part + 1) * V_) / NPARTS;

    float bestS = NEGF;
    int bestF = 0;
    int bestV = 0;

    for (int v = vlo; v < vhi; v++) {
        uint4 q0 = __ldg(&g_seg[v * 2]);
        uint4 q1 = __ldg(&g_seg[v * 2 + 1]);
        int len = (int)q1.y;
        float inv = __uint_as_float(q1.z);
        unsigned u;
        float acc;
        u = q0.x & 0xFFFFu;  acc  = base[0 * PB_STRIDE + u];
        u = q0.x >> 16;      acc += base[1 * PB_STRIDE + u];
        u = q0.y & 0xFFFFu;  acc += base[2 * PB_STRIDE + u];
        u = q0.y >> 16;      acc += base[3 * PB_STRIDE + u];
        if (len > 4) { u = q0.z & 0xFFFFu;  acc += base[4 * PB_STRIDE + u];
        if (len > 5) { u = q0.z >> 16;      acc += base[5 * PB_STRIDE + u];
        if (len > 6) { u = q0.w & 0xFFFFu;  acc += base[6 * PB_STRIDE + u];
        if (len > 7) { u = q0.w >> 16;      acc += base[7 * PB_STRIDE + u];
        if (len > 8) { u = q1.x & 0xFFFFu;  acc += base[8 * PB_STRIDE + u];
        if (len > 9) { u = q1.x >> 16;      acc += base[9 * PB_STRIDE + u]; }}}}}}
        float score = acc * inv;
        if (l + len <= Lb) {                       // viable span
            int f = l * E_ + (len - 4);            // flat (l,e) index
            bool better = (score > bestS) || ((score == bestS) && (f < bestF));
            if (better) { bestS = score; bestF = f; bestV = v; }
        }
    }

    unsigned long long key = pack_key(bestS, bestF, bestV);
    #pragma unroll
    for (int o = 16; o; o >>= 1) {
        unsigned long long other = __shfl_down_sync(0xffffffffu, key, o);
        if (other > key) key = other;
    }
    if (lane == 0) atomicMax(&g_keys[b], key);
}

// ---------------------------------------------------------------------------
// Kernel 5: decode per-batch keys into the 5 outputs (80 f32 total)
// layout: [scores(16) | starts(16) | ends(16) | any_matched(16) | vocab(16)]
// ---------------------------------------------------------------------------
__global__ void k_out(float* __restrict__ out) {
    int t = threadIdx.x;
    if (t >= B_) return;
    unsigned long long key = g_keys[t];
    int v = 16383 - (int)(key & 0x3FFFull);
    int f = 511 - (int)((key >> 14) & 0x1FFull);
    unsigned mono = (unsigned)(key >> 23);
    unsigned fb = (mono & 0x80000000u) ? (mono & 0x7FFFFFFFu) : ~mono;
    float score = __uint_as_float(fb);
    int l = f / E_;
    int e = f - l * E_;
    out[0 * B_ + t] = score;
    out[1 * B_ + t] = (float)l;                    // best_starts
    out[2 * B_ + t] = (float)(l + e + 3);          // best_ends
    out[3 * B_ + t] = (score > 0.05f) ? 1.0f : 0.0f; // any_matched == best>thresh
    out[4 * B_ + t] = (float)v;                    // best_vocab
}

// ---------------------------------------------------------------------------
extern "C" void kernel_launch(void* const* d_in, const int* in_sizes, int n_in,
                              void* d_out, int out_size) {
    const float* x       = (const float*)d_in[0];   // [16,64,60]
    const float* uf      = (const float*)d_in[1];   // [600,60]
    const float* W       = (const float*)d_in[2];   // [60,256]
    const int*   lengths = (const int*)d_in[3];     // [16]
    const int*   segs    = (const int*)d_in[4];     // [10000,10]
    const int*   vlen    = (const int*)d_in[5];     // [10000]
    float* out = (float*)d_out;

    k_embed<<<1024 + 600, 256>>>(x, uf, W);
    k_sim_gemm<<<dim3(10, 16), 256>>>();
    k_prep<<<(V_ + 255) / 256, 256>>>(segs, vlen);
    k_init_keys<<<1, 32>>>();
    cudaFuncSetAttribute(k_phaseB, cudaFuncAttributeMaxDynamicSharedMemorySize, PB_SMEM);
    k_phaseB<<<dim3(8, 2, 16), 512, PB_SMEM>>>(lengths);
    k_out<<<1, 32>>>(out);
}

// round 2
// speedup vs baseline: 1.0861x; 1.0861x over previous
#include <cuda_runtime.h>
#include <cstdint>

// Problem constants
#define B_  16
#define L_  64
#define F_  60
#define D_  256
#define U_  600
#define V_  10000
#define E_  7        // MAX_LEN - MIN_LEN + 1
#define NEGF (-1e9f)

// Scratch (device globals: no allocation allowed)
__device__ float g_wn[1024 * 256];          // normalized word reprs [B*L, D]
__device__ float g_un[600 * 256];           // normalized unit reprs [U, D]
__device__ float g_sim[1024 * 600];         // sim [B*L, U]
__device__ uint4 g_seg[10000 * 2];          // packed vocab: 10 u16 units, len, 1/len
__device__ unsigned long long g_keys[16];   // per-batch best candidate key
__device__ unsigned g_done;                 // phaseB completion counter

// monotone float->u32 (orders like float compare, all non-NaN)
__device__ __forceinline__ unsigned f2mono(float f) {
    unsigned b = __float_as_uint(f);
    return (b & 0x80000000u) ? ~b : (b | 0x80000000u);
}
__device__ __forceinline__ unsigned long long pack_key(float s, int f, int v) {
    return ((unsigned long long)f2mono(s) << 23)
         | ((unsigned long long)(511 - f) << 14)
         | (unsigned long long)(16383 - v);
}

// ---------------------------------------------------------------------------
// Kernel 1 (fused setup):
//   blocks   0..127 : embed+normalize 8 word rows each   (1024 rows)
//   blocks 128..202 : embed+normalize 8 unit rows each   (600 rows)
//   blocks 203..242 : pack vocab table (256 words each); block 242 also
//                     initializes g_keys and resets g_done.
// ---------------------------------------------------------------------------
#define EMB_WBLK 128
#define EMB_UBLK 75
#define PREP_BLK 40
#define SETUP_GRID (EMB_WBLK + EMB_UBLK + PREP_BLK)   // 243

__global__ void __launch_bounds__(256) k_setup(const float* __restrict__ x,
                                               const float* __restrict__ uf,
                                               const float* __restrict__ W,
                                               const int* __restrict__ segs,
                                               const int* __restrict__ vlen) {
    int blk = blockIdx.x;
    if (blk < EMB_WBLK + EMB_UBLK) {
        // ---- embed 8 rows, reuse each W element for 8 FMAs ----
        __shared__ float feat[8 * F_];
        __shared__ float spart[8 * 8];
        __shared__ float sinv[8];
        const float* src;
        float* dst;
        if (blk < EMB_WBLK) { int r0 = blk * 8;              src = x  + r0 * F_; dst = g_wn + r0 * D_; }
        else                { int r0 = (blk - EMB_WBLK) * 8; src = uf + r0 * F_; dst = g_un + r0 * D_; }
        int d = threadIdx.x;               // 0..255 == D_
        for (int i = d; i < 8 * F_; i += 256) feat[i] = src[i];
        __syncthreads();
        float val[8] = {};
        #pragma unroll
        for (int f = 0; f < F_; f++) {
            float wv = W[f * D_ + d];
            #pragma unroll
            for (int r = 0; r < 8; r++) val[r] = fmaf(feat[r * F_ + f], wv, val[r]);
        }
        int lane = d & 31, warp = d >> 5;
        #pragma unroll
        for (int r = 0; r < 8; r++) {
            float v2 = val[r] * val[r];
            #pragma unroll
            for (int o = 16; o; o >>= 1) v2 += __shfl_down_sync(0xffffffffu, v2, o);
            if (lane == 0) spart[r * 8 + warp] = v2;
        }
        __syncthreads();
        if (d < 8) {
            float s = 0.f;
            #pragma unroll
            for (int i = 0; i < 8; i++) s += spart[d * 8 + i];
            sinv[d] = 1.0f / (sqrtf(s) + 1e-8f);
        }
        __syncthreads();
        #pragma unroll
        for (int r = 0; r < 8; r++) dst[r * D_ + d] = val[r] * sinv[r];
    } else {
        // ---- pack vocab ----
        int pb = blk - (EMB_WBLK + EMB_UBLK);
        int v = pb * 256 + threadIdx.x;
        if (v < V_) {
            unsigned w[5];
            #pragma unroll
            for (int p = 0; p < 5; p++) {
                unsigned lo = (unsigned)segs[v * 10 + 2 * p];
                unsigned hi = (unsigned)segs[v * 10 + 2 * p + 1];
                w[p] = (lo & 0xFFFFu) | (hi << 16);
            }
            int len = vlen[v];
            float inv = 1.0f / (float)len;
            g_seg[v * 2]     = make_uint4(w[0], w[1], w[2], w[3]);
            g_seg[v * 2 + 1] = make_uint4(w[4], (unsigned)len, __float_as_uint(inv), 0u);
        }
        if (pb == PREP_BLK - 1) {   // last prep block: threads 32.. are idle (v>=9999+)
            int t = threadIdx.x;
            if (t >= 32 && t < 48) g_keys[t - 32] = pack_key(NEGF, 0, 0);
            if (t == 63) g_done = 0u;
        }
    }
}

// ---------------------------------------------------------------------------
// Kernel 2: sim = wn @ un^T  (M=1024, N=600, K=256), 64x64 tile,
// 256 threads, 4x4 per thread.  grid = (10, 16)
// ---------------------------------------------------------------------------
__global__ void k_sim_gemm() {
    __shared__ float As[16 * 64];
    __shared__ float Bs[16 * 64];
    int tid = threadIdx.x;
    int n0 = blockIdx.x * 64;
    int m0 = blockIdx.y * 64;
    int tx = tid & 15, ty = tid >> 4;      // 16x16 thread grid
    int lm = tid >> 2;                     // 0..63 : row of tile to load
    int lk = (tid & 3) * 4;                // 0,4,8,12 : k-offset (float4)
    float acc[4][4] = {};
    for (int k0 = 0; k0 < 256; k0 += 16) {
        float4 a = *(const float4*)(g_wn + (m0 + lm) * 256 + k0 + lk);
        float4 bv = make_float4(0.f, 0.f, 0.f, 0.f);
        int n = n0 + lm;
        if (n < U_) bv = *(const float4*)(g_un + n * 256 + k0 + lk);
        __syncthreads();   // previous compute done before overwrite
        As[(lk + 0) * 64 + lm] = a.x;
        As[(lk + 1) * 64 + lm] = a.y;
        As[(lk + 2) * 64 + lm] = a.z;
        As[(lk + 3) * 64 + lm] = a.w;
        Bs[(lk + 0) * 64 + lm] = bv.x;
        Bs[(lk + 1) * 64 + lm] = bv.y;
        Bs[(lk + 2) * 64 + lm] = bv.z;
        Bs[(lk + 3) * 64 + lm] = bv.w;
        __syncthreads();
        #pragma unroll
        for (int kk = 0; kk < 16; kk++) {
            float ar[4], br[4];
            #pragma unroll
            for (int i = 0; i < 4; i++) ar[i] = As[kk * 64 + ty * 4 + i];
            #pragma unroll
            for (int j = 0; j < 4; j++) br[j] = Bs[kk * 64 + tx * 4 + j];
            #pragma unroll
            for (int i = 0; i < 4; i++)
                #pragma unroll
                for (int j = 0; j < 4; j++)
                    acc[i][j] = fmaf(ar[i], br[j], acc[i][j]);
        }
    }
    #pragma unroll
    for (int i = 0; i < 4; i++) {
        int m = m0 + ty * 4 + i;
        #pragma unroll
        for (int j = 0; j < 4; j++) {
            int n = n0 + tx * 4 + j;
            if (n < U_) g_sim[m * U_ + n] = acc[i][j];
        }
    }
}

// ---------------------------------------------------------------------------
// Kernel 3 (hot): per (b, 32-l tile, vocab chunk) CTA.
// smem holds sim rows [l0 .. l0+40] padded to stride 601 (odd mod 32 ->
// conflict-free: the 32 lanes = 32 consecutive l's gather the same unit).
// grid = (VC=9, 2, 16) = 288 CTAs ~= exactly 2 per SM at occupancy 2.
// Last-finishing CTA decodes g_keys into the output (fused epilogue).
// ---------------------------------------------------------------------------
#define PB_ROWS 41
#define PB_STRIDE 601
#define PB_SMEM (PB_ROWS * PB_STRIDE * 4)
#define VC_ 9
#define NPARTS (VC_ * 16)        // 144 warp-partitions of the vocab
#define NCTA_PB (VC_ * 2 * 16)   // 288

__global__ void __launch_bounds__(512, 2) k_phaseB(const int* __restrict__ lengths,
                                                   float* __restrict__ out) {
    extern __shared__ float S[];
    int vc = blockIdx.x;   // 0..8
    int lt = blockIdx.y;   // 0..1
    int b  = blockIdx.z;   // 0..15
    int l0 = lt * 32;
    const float* simb = g_sim + (b * L_) * U_;
    // stage sim tile (rows >= L_ are the zero padding of the reference)
    for (int i = threadIdx.x; i < PB_ROWS * U_; i += 512) {
        int r = i / U_;
        int u = i - r * U_;
        int gl = l0 + r;
        S[r * PB_STRIDE + u] = (gl < L_) ? simb[gl * U_ + u] : 0.f;
    }
    __syncthreads();

    int warp = threadIdx.x >> 5;
    int lane = threadIdx.x & 31;
    int l = l0 + lane;
    int Lb = __ldg(&lengths[b]);
    const float* base = S + lane * PB_STRIDE;

    int part = vc * 16 + warp;
    int vlo = (part * V_) / NPARTS;
    int vhi = ((part + 1) * V_) / NPARTS;

    float bestS = NEGF;
    int bestF = 0;
    int bestV = 0;

    for (int v = vlo; v < vhi; v++) {
        uint4 q0 = __ldg(&g_seg[v * 2]);
        uint4 q1 = __ldg(&g_seg[v * 2 + 1]);
        int len = (int)q1.y;
        float inv = __uint_as_float(q1.z);
        unsigned u;
        float acc;
        u = q0.x & 0xFFFFu;  acc  = base[0 * PB_STRIDE + u];
        u = q0.x >> 16;      acc += base[1 * PB_STRIDE + u];
        u = q0.y & 0xFFFFu;  acc += base[2 * PB_STRIDE + u];
        u = q0.y >> 16;      acc += base[3 * PB_STRIDE + u];
        if (len > 4) { u = q0.z & 0xFFFFu;  acc += base[4 * PB_STRIDE + u];
        if (len > 5) { u = q0.z >> 16;      acc += base[5 * PB_STRIDE + u];
        if (len > 6) { u = q0.w & 0xFFFFu;  acc += base[6 * PB_STRIDE + u];
        if (len > 7) { u = q0.w >> 16;      acc += base[7 * PB_STRIDE + u];
        if (len > 8) { u = q1.x & 0xFFFFu;  acc += base[8 * PB_STRIDE + u];
        if (len > 9) { u = q1.x >> 16;      acc += base[9 * PB_STRIDE + u]; }}}}}}
        float score = acc * inv;
        if (l + len <= Lb) {                       // viable span
            int f = l * E_ + (len - 4);            // flat (l,e) index
            bool better = (score > bestS) || ((score == bestS) && (f < bestF));
            if (better) { bestS = score; bestF = f; bestV = v; }
        }
    }

    unsigned long long key = pack_key(bestS, bestF, bestV);
    #pragma unroll
    for (int o = 16; o; o >>= 1) {
        unsigned long long other = __shfl_down_sync(0xffffffffu, key, o);
        if (other > key) key = other;
    }
    if (lane == 0) atomicMax(&g_keys[b], key);

    // -------- fused epilogue: last CTA to finish decodes the outputs --------
    __syncthreads();                 // all warps of this CTA have posted atomics
    __threadfence();                 // make them globally visible before count
    __shared__ unsigned s_old;
    if (threadIdx.x == 0) s_old = atomicAdd(&g_done, 1u);
    __syncthreads();
    if (s_old == NCTA_PB - 1) {
        int t = threadIdx.x;
        if (t < B_) {
            // coherent read of the final key (atomic RMW bypasses L1)
            unsigned long long k2 = atomicAdd(&g_keys[t], 0ull);
            int v = 16383 - (int)(k2 & 0x3FFFull);
            int f = 511 - (int)((k2 >> 14) & 0x1FFull);
            unsigned mono = (unsigned)(k2 >> 23);
            unsigned fb = (mono & 0x80000000u) ? (mono & 0x7FFFFFFFu) : ~mono;
            float score = __uint_as_float(fb);
            int ll = f / E_;
            int e = f - ll * E_;
            out[0 * B_ + t] = score;
            out[1 * B_ + t] = (float)ll;                      // best_starts
            out[2 * B_ + t] = (float)(ll + e + 3);            // best_ends
            out[3 * B_ + t] = (score > 0.05f) ? 1.0f : 0.0f;  // any_matched
            out[4 * B_ + t] = (float)v;                       // best_vocab
        }
    }
}

// ---------------------------------------------------------------------------
extern "C" void kernel_launch(void* const* d_in, const int* in_sizes, int n_in,
                              void* d_out, int out_size) {
    const float* x       = (const float*)d_in[0];   // [16,64,60]
    const float* uf      = (const float*)d_in[1];   // [600,60]
    const float* W       = (const float*)d_in[2];   // [60,256]
    const int*   lengths = (const int*)d_in[3];     // [16]
    const int*   segs    = (const int*)d_in[4];     // [10000,10]
    const int*   vlen    = (const int*)d_in[5];     // [10000]
    float* out = (float*)d_out;

    k_setup<<<SETUP_GRID, 256>>>(x, uf, W, segs, vlen);
    k_sim_gemm<<<dim3(10, 16), 256>>>();
    cudaFuncSetAttribute(k_phaseB, cudaFuncAttributeMaxDynamicSharedMemorySize, PB_SMEM);
    k_phaseB<<<dim3(VC_, 2, 16), 512, PB_SMEM>>>(lengths, out);
}